// round 3
// baseline (speedup 1.0000x reference)
#include <cuda_runtime.h>
#include <cstdint>

// ---------------- problem constants ----------------
#define NN   50000
#define EE   800000
#define FIN  128
#define HH   4
#define CC1  64
#define CC2  32
#define NEG_SLOPE 0.2f
#define EPSV 1e-16f

// ---------------- device scratch (no allocs allowed) ----------------
__device__ float g_feat[NN * HH * CC1];    // layer1: h1 [N,4,64]; layer2 reuse: h2 [N,4,32]
__device__ float g_accum[NN * HH * CC1];   // scatter accumulator
__device__ float g_hmid[NN * CC1];         // layer1 output after mean+bias+relu [N,64]
__device__ float g_ex[EE * HH];            // per-edge exp(logit) [E,4]
__device__ float g_as[NN * HH];
__device__ float g_ad[NN * HH];
__device__ float g_denom[NN * HH];
__device__ int   g_src[EE];
__device__ int   g_dst[EE];

// ---------------- kernels ----------------

// Decode edge_index into int src/dst. Detects int32 vs int64 on device:
// if the first 8 words interpreted as int64 are all in [0, NN), it's int64
// (for int32 data each such word contains a random index in its high half,
// so false-positive probability is ~(1/NN)^8 ~= 0).
__global__ void decode_edges_kernel(const void* __restrict__ ei_raw,
                                    int* __restrict__ src, int* __restrict__ dst) {
    const long long* p64 = (const long long*)ei_raw;
    bool is64 = true;
#pragma unroll
    for (int k = 0; k < 8; k++) {
        long long v = p64[k];
        if (v < 0 || v >= NN) { is64 = false; break; }
    }
    int i = blockIdx.x * blockDim.x + threadIdx.x;
    int stride = gridDim.x * blockDim.x;
    if (is64) {
        for (; i < EE; i += stride) {
            src[i] = (int)p64[i];
            dst[i] = (int)p64[EE + i];
        }
    } else {
        const int* p32 = (const int*)ei_raw;
        for (; i < EE; i += stride) {
            src[i] = p32[i];
            dst[i] = p32[EE + i];
        }
    }
}

// C[n,M] = A[n,K] @ B[K,M]; BM=BN=64, BK=16, 256 threads, 4x4 microtile.
__global__ void gemm_kernel(const float* __restrict__ A, const float* __restrict__ B,
                            float* __restrict__ C, int n, int K, int M) {
    const int BM = 64, BN = 64, BK = 16, TM = 4, TN = 4;
    __shared__ float As[BK][BM];
    __shared__ float Bs[BK][BN];
    int tx = threadIdx.x % 16;
    int ty = threadIdx.x / 16;
    int rowBase = blockIdx.y * BM;
    int colBase = blockIdx.x * BN;
    float acc[TM][TN];
#pragma unroll
    for (int i = 0; i < TM; i++)
#pragma unroll
        for (int j = 0; j < TN; j++) acc[i][j] = 0.f;

    for (int k0 = 0; k0 < K; k0 += BK) {
        for (int i = threadIdx.x; i < BM * BK; i += 256) {
            int m = i / BK, kk = i % BK;
            int r = rowBase + m;
            As[kk][m] = (r < n) ? A[(size_t)r * K + k0 + kk] : 0.f;
        }
        for (int i = threadIdx.x; i < BK * BN; i += 256) {
            int kk = i / BN, c = i % BN;
            Bs[kk][c] = B[(size_t)(k0 + kk) * M + colBase + c];
        }
        __syncthreads();
#pragma unroll
        for (int kk = 0; kk < BK; kk++) {
            float a[TM], b[TN];
#pragma unroll
            for (int i = 0; i < TM; i++) a[i] = As[kk][ty * TM + i];
#pragma unroll
            for (int j = 0; j < TN; j++) b[j] = Bs[kk][tx * TN + j];
#pragma unroll
            for (int i = 0; i < TM; i++)
#pragma unroll
                for (int j = 0; j < TN; j++) acc[i][j] += a[i] * b[j];
        }
        __syncthreads();
    }
#pragma unroll
    for (int i = 0; i < TM; i++) {
        int r = rowBase + ty * TM + i;
        if (r < n) {
#pragma unroll
            for (int j = 0; j < TN; j++)
                C[(size_t)r * M + colBase + tx * TN + j] = acc[i][j];
        }
    }
}

// a_s[n,h] = dot(h[n,h,:], att_src[h,:]); same for a_d. One warp per (n,h).
__global__ void att_dots_kernel(const float* __restrict__ feat,
                                const float* __restrict__ att_s,
                                const float* __restrict__ att_d,
                                float* __restrict__ as_o, float* __restrict__ ad_o, int C) {
    int w = (blockIdx.x * blockDim.x + threadIdx.x) >> 5;
    int lane = threadIdx.x & 31;
    if (w >= NN * HH) return;
    int node = w / HH, h = w % HH;
    const float* hp = feat + (size_t)node * HH * C + h * C;
    float s = 0.f, d = 0.f;
    for (int c = lane; c < C; c += 32) {
        float v = hp[c];
        s += v * att_s[h * C + c];
        d += v * att_d[h * C + c];
    }
#pragma unroll
    for (int o = 16; o; o >>= 1) {
        s += __shfl_down_sync(0xffffffffu, s, o);
        d += __shfl_down_sync(0xffffffffu, d, o);
    }
    if (lane == 0) { as_o[w] = s; ad_o[w] = d; }
}

__global__ void zero_kernel(float* __restrict__ p, int n) {
    int i = blockIdx.x * blockDim.x + threadIdx.x;
    int stride = gridDim.x * blockDim.x;
    for (; i < n; i += stride) p[i] = 0.f;
}

// per edge: e = leakyrelu(a_s[src]+a_d[dst]); ex = exp(e); denom[dst] += ex
__global__ void edge_denom_kernel(const int* __restrict__ srcs, const int* __restrict__ dsts,
                                  const float* __restrict__ as_i,
                                  const float* __restrict__ ad_i,
                                  float* __restrict__ ex_o, float* __restrict__ denom) {
    int i = blockIdx.x * blockDim.x + threadIdx.x;
    if (i >= EE) return;
    int src = srcs[i];
    int dst = dsts[i];
    float4 av = ((const float4*)as_i)[src];
    float4 dv = ((const float4*)ad_i)[dst];
    float e0 = av.x + dv.x, e1 = av.y + dv.y, e2 = av.z + dv.z, e3 = av.w + dv.w;
    e0 = e0 > 0.f ? e0 : NEG_SLOPE * e0;
    e1 = e1 > 0.f ? e1 : NEG_SLOPE * e1;
    e2 = e2 > 0.f ? e2 : NEG_SLOPE * e2;
    e3 = e3 > 0.f ? e3 : NEG_SLOPE * e3;
    float4 exv = make_float4(__expf(e0), __expf(e1), __expf(e2), __expf(e3));
    ((float4*)ex_o)[i] = exv;
    atomicAdd(((float4*)denom) + dst, exv);
}

// warp per edge: accum[dst,h,c] += alpha[h] * feat[src,h,c]  (float4 atomics)
__global__ void edge_scatter_kernel(const int* __restrict__ srcs, const int* __restrict__ dsts,
                                    const float* __restrict__ ex_i,
                                    const float* __restrict__ denom,
                                    const float* __restrict__ feat,
                                    float* __restrict__ accum,
                                    int C) {
    int w = (blockIdx.x * blockDim.x + threadIdx.x) >> 5;
    int lane = threadIdx.x & 31;
    if (w >= EE) return;
    int src = srcs[w];
    int dst = dsts[w];
    float alpha = 0.f;
    if (lane < HH)
        alpha = ex_i[(size_t)w * HH + lane] / (denom[(size_t)dst * HH + lane] + EPSV);
    const float4* fsrc = (const float4*)(feat + (size_t)src * HH * C);
    float4* adst = (float4*)(accum + (size_t)dst * HH * C);
    int cdiv = C >> 2;
    int nchunk = HH * cdiv;
    for (int j = lane; j < nchunk; j += 32) {
        int hd = j / cdiv;
        float al = __shfl_sync(0xffffffffu, alpha, hd);
        float4 v = fsrc[j];
        float4 r = make_float4(v.x * al, v.y * al, v.z * al, v.w * al);
        atomicAdd(adst + j, r);
    }
}

// out[n,c] = mean_h accum[n,h,c] + bias[c]; optional relu
__global__ void finalize_kernel(const float* __restrict__ accum,
                                const float* __restrict__ bias,
                                float* __restrict__ out, int C, int do_relu) {
    int idx = blockIdx.x * blockDim.x + threadIdx.x;
    if (idx >= NN * C) return;
    int node = idx / C, c = idx % C;
    const float* p = accum + (size_t)node * HH * C + c;
    float v = 0.25f * (p[0] + p[C] + p[2 * C] + p[3 * C]);
    v += bias[c];
    if (do_relu) v = fmaxf(v, 0.f);
    out[idx] = v;
}

// ---------------- host launcher ----------------
extern "C" void kernel_launch(void* const* d_in, const int* in_sizes, int n_in,
                              void* d_out, int out_size) {
    const float* x   = (const float*)d_in[0];
    const void*  ei  = d_in[1];
    const float* W1  = (const float*)d_in[2];
    const float* as1 = (const float*)d_in[3];
    const float* ad1 = (const float*)d_in[4];
    const float* b1  = (const float*)d_in[5];
    const float* W2  = (const float*)d_in[6];
    const float* as2 = (const float*)d_in[7];
    const float* ad2 = (const float*)d_in[8];
    const float* b2  = (const float*)d_in[9];
    float* out = (float*)d_out;

    float *feat, *accum, *hmid, *exb, *asb, *adb, *denom;
    int *srcp, *dstp;
    cudaGetSymbolAddress((void**)&feat,  g_feat);
    cudaGetSymbolAddress((void**)&accum, g_accum);
    cudaGetSymbolAddress((void**)&hmid,  g_hmid);
    cudaGetSymbolAddress((void**)&exb,   g_ex);
    cudaGetSymbolAddress((void**)&asb,   g_as);
    cudaGetSymbolAddress((void**)&adb,   g_ad);
    cudaGetSymbolAddress((void**)&denom, g_denom);
    cudaGetSymbolAddress((void**)&srcp,  g_src);
    cudaGetSymbolAddress((void**)&dstp,  g_dst);

    decode_edges_kernel<<<2048, 256>>>(ei, srcp, dstp);

    // ---------------- layer 1 ----------------
    {
        const int C = CC1, M = HH * CC1;  // 256
        dim3 ggrid(M / 64, (NN + 63) / 64);
        gemm_kernel<<<ggrid, 256>>>(x, W1, feat, NN, FIN, M);

        att_dots_kernel<<<(NN * HH * 32 + 255) / 256, 256>>>(feat, as1, ad1, asb, adb, C);

        zero_kernel<<<2048, 256>>>(denom, NN * HH);
        zero_kernel<<<4096, 256>>>(accum, NN * HH * C);

        edge_denom_kernel<<<(EE + 255) / 256, 256>>>(srcp, dstp, asb, adb, exb, denom);

        edge_scatter_kernel<<<(EE * 32 + 255) / 256, 256>>>(srcp, dstp, exb, denom, feat, accum, C);

        finalize_kernel<<<(NN * C + 255) / 256, 256>>>(accum, b1, hmid, C, 1);
    }

    // ---------------- layer 2 ----------------
    {
        const int C = CC2, M = HH * CC2;  // 128
        dim3 ggrid(M / 64, (NN + 63) / 64);
        gemm_kernel<<<ggrid, 256>>>(hmid, W2, feat, NN, CC1, M);

        att_dots_kernel<<<(NN * HH * 32 + 255) / 256, 256>>>(feat, as2, ad2, asb, adb, C);

        zero_kernel<<<2048, 256>>>(denom, NN * HH);
        zero_kernel<<<4096, 256>>>(accum, NN * HH * C);

        edge_denom_kernel<<<(EE + 255) / 256, 256>>>(srcp, dstp, asb, adb, exb, denom);

        edge_scatter_kernel<<<(EE * 32 + 255) / 256, 256>>>(srcp, dstp, exb, denom, feat, accum, C);

        finalize_kernel<<<(NN * C + 255) / 256, 256>>>(accum, b2, out, C, 0);
    }
}

// round 5
// speedup vs baseline: 2.3803x; 2.3803x over previous
#include <cuda_runtime.h>
#include <cstdint>

// ---------------- problem constants ----------------
#define NN   50000
#define EE   800000
#define FIN  128
#define HH   4
#define CC1  64
#define CC2  32
#define NEG_SLOPE 0.2f
#define EPSV 1e-16f

// ---------------- device scratch (no allocs allowed) ----------------
__device__ float g_feat[NN * HH * CC1];    // layer1: h1 [N,256]; layer2 reuse: h2 [N,128]
__device__ float g_hmid[NN * CC1];         // layer1 output after mean+bias+relu [N,64]
__device__ float g_as[NN * HH];
__device__ float g_ad[NN * HH];
__device__ int   g_src[EE];
__device__ int   g_dst[EE];
__device__ int   g_deg[NN];
__device__ int   g_rowptr[NN + 1];
__device__ int   g_cursor[NN];
__device__ int   g_csr_src[EE];

// ---------------- kernels ----------------

__global__ void zero_deg_kernel(int* __restrict__ deg) {
    int i = blockIdx.x * blockDim.x + threadIdx.x;
    int stride = gridDim.x * blockDim.x;
    for (; i < NN; i += stride) deg[i] = 0;
}

// Decode edge_index into int src/dst + in-degree histogram.
// Detects int32 vs int64 on device (false-positive prob ~(1/NN)^8 ~= 0).
__global__ void decode_hist_kernel(const void* __restrict__ ei_raw,
                                   int* __restrict__ src, int* __restrict__ dst,
                                   int* __restrict__ deg) {
    const long long* p64 = (const long long*)ei_raw;
    bool is64 = true;
#pragma unroll
    for (int k = 0; k < 8; k++) {
        long long v = p64[k];
        if (v < 0 || v >= NN) { is64 = false; break; }
    }
    int i = blockIdx.x * blockDim.x + threadIdx.x;
    int stride = gridDim.x * blockDim.x;
    if (is64) {
        for (; i < EE; i += stride) {
            int s = (int)p64[i];
            int d = (int)p64[EE + i];
            src[i] = s; dst[i] = d;
            atomicAdd(&deg[d], 1);
        }
    } else {
        const int* p32 = (const int*)ei_raw;
        for (; i < EE; i += stride) {
            int s = p32[i];
            int d = p32[EE + i];
            src[i] = s; dst[i] = d;
            atomicAdd(&deg[d], 1);
        }
    }
}

// Single-block streaming exclusive scan of deg -> rowptr (+ cursor copy).
__global__ void scan_kernel(const int* __restrict__ deg,
                            int* __restrict__ rowptr, int* __restrict__ cursor) {
    __shared__ int sm[1024];
    __shared__ int carry;
    int t = threadIdx.x;
    if (t == 0) carry = 0;
    __syncthreads();
    for (int base = 0; base < NN; base += 1024) {
        int i = base + t;
        int v = (i < NN) ? deg[i] : 0;
        sm[t] = v;
        __syncthreads();
        // Hillis-Steele inclusive scan
#pragma unroll
        for (int off = 1; off < 1024; off <<= 1) {
            int x = (t >= off) ? sm[t - off] : 0;
            __syncthreads();
            sm[t] += x;
            __syncthreads();
        }
        int incl = sm[t];
        int tot = sm[1023];
        __syncthreads();          // everyone has read sm before next-tile overwrite
        int excl = incl - v + carry;
        if (i < NN) { rowptr[i] = excl; cursor[i] = excl; }
        if (t == 0) carry += tot;
        __syncthreads();
    }
    if (t == 0) rowptr[NN] = EE;
}

// Scatter edge source ids into CSR slots grouped by dst.
__global__ void fill_csr_kernel(const int* __restrict__ src, const int* __restrict__ dst,
                                int* __restrict__ cursor, int* __restrict__ csr_src) {
    int i = blockIdx.x * blockDim.x + threadIdx.x;
    int stride = gridDim.x * blockDim.x;
    for (; i < EE; i += stride) {
        int d = dst[i];
        int slot = atomicAdd(&cursor[d], 1);
        csr_src[slot] = src[i];
    }
}

// C[n,M] = A[n,K] @ B[K,M]; BM=128, BN=64, BK=16, 256 threads, 8x4 microtile.
__global__ void __launch_bounds__(256) gemm_kernel(
        const float* __restrict__ A, const float* __restrict__ B,
        float* __restrict__ C, int n, int K, int M) {
    __shared__ float As[16][128];
    __shared__ float Bs[16][64];
    int tid = threadIdx.x;
    int tx = tid & 15;        // col group (4 cols)
    int ty = tid >> 4;        // row group (8 rows)
    int rowBase = blockIdx.y * 128;
    int colBase = blockIdx.x * 64;
    float acc[8][4];
#pragma unroll
    for (int i = 0; i < 8; i++)
#pragma unroll
        for (int j = 0; j < 4; j++) acc[i][j] = 0.f;

    for (int k0 = 0; k0 < K; k0 += 16) {
        // A tile: 128x16 floats = 512 float4, 2 per thread, transposed into As
#pragma unroll
        for (int q = 0; q < 2; q++) {
            int idx = tid + q * 256;
            int r = idx >> 2;
            int kq = idx & 3;
            int row = rowBase + r;
            float4 v = (row < n) ? ((const float4*)(A + (size_t)row * K + k0))[kq]
                                 : make_float4(0.f, 0.f, 0.f, 0.f);
            As[kq * 4 + 0][r] = v.x;
            As[kq * 4 + 1][r] = v.y;
            As[kq * 4 + 2][r] = v.z;
            As[kq * 4 + 3][r] = v.w;
        }
        // B tile: 16x64 floats = 256 float4, 1 per thread
        {
            int r = tid >> 4;
            int cq = tid & 15;
            float4 v = ((const float4*)(B + (size_t)(k0 + r) * M + colBase))[cq];
            ((float4*)&Bs[r][0])[cq] = v;
        }
        __syncthreads();
#pragma unroll
        for (int kk = 0; kk < 16; kk++) {
            float a[8], b[4];
            float4 a0 = ((const float4*)&As[kk][0])[ty * 2];
            float4 a1 = ((const float4*)&As[kk][0])[ty * 2 + 1];
            a[0] = a0.x; a[1] = a0.y; a[2] = a0.z; a[3] = a0.w;
            a[4] = a1.x; a[5] = a1.y; a[6] = a1.z; a[7] = a1.w;
            float4 bv = ((const float4*)&Bs[kk][0])[tx];
            b[0] = bv.x; b[1] = bv.y; b[2] = bv.z; b[3] = bv.w;
#pragma unroll
            for (int i = 0; i < 8; i++)
#pragma unroll
                for (int j = 0; j < 4; j++) acc[i][j] += a[i] * b[j];
        }
        __syncthreads();
    }
#pragma unroll
    for (int i = 0; i < 8; i++) {
        int r = rowBase + ty * 8 + i;
        if (r < n) {
            float4 v = make_float4(acc[i][0], acc[i][1], acc[i][2], acc[i][3]);
            ((float4*)(C + (size_t)r * M + colBase))[tx] = v;
        }
    }
}

// a_s[n,h] = dot(h[n,h,:], att_src[h,:]); same for a_d. One warp per (n,h).
__global__ void att_dots_kernel(const float* __restrict__ feat,
                                const float* __restrict__ att_s,
                                const float* __restrict__ att_d,
                                float* __restrict__ as_o, float* __restrict__ ad_o, int C) {
    int w = (blockIdx.x * blockDim.x + threadIdx.x) >> 5;
    int lane = threadIdx.x & 31;
    if (w >= NN * HH) return;
    int node = w / HH, h = w % HH;
    const float* hp = feat + (size_t)node * HH * C + h * C;
    float s = 0.f, d = 0.f;
    for (int c = lane; c < C; c += 32) {
        float v = hp[c];
        s += v * att_s[h * C + c];
        d += v * att_d[h * C + c];
    }
#pragma unroll
    for (int o = 16; o; o >>= 1) {
        s += __shfl_down_sync(0xffffffffu, s, o);
        d += __shfl_down_sync(0xffffffffu, d, o);
    }
    if (lane == 0) { as_o[w] = s; ad_o[w] = d; }
}

// Fused pull-mode GAT aggregation: one block (128 thr) per destination node.
// Computes ex = exp(leakyrelu(a_s[src]+a_d[dst])) inline, accumulates
// sum(ex * h[src]) and denom in registers, writes head-mean + bias (+relu) once.
template <int C>
__global__ void __launch_bounds__(128) gat_aggregate_kernel(
        const int* __restrict__ rowptr,
        const int* __restrict__ csr_src,
        const float* __restrict__ as_i,
        const float* __restrict__ ad_i,
        const float* __restrict__ feat,
        const float* __restrict__ bias,
        float* __restrict__ out, int do_relu) {
    constexpr int V = C / 32;            // floats per thread (2 for C=64, 1 for C=32)
    __shared__ float sm[HH * C];
    const int node = blockIdx.x;
    const int t = threadIdx.x;
    const int head = t >> 5;             // warp w handles head w
    const float adh = ad_i[node * HH + head];
    int beg = rowptr[node], end = rowptr[node + 1];
    float acc[V];
#pragma unroll
    for (int j = 0; j < V; j++) acc[j] = 0.f;
    float denom = 0.f;

    int e = beg;
    for (; e + 2 <= end; e += 2) {
        int s0 = __ldg(&csr_src[e]), s1 = __ldg(&csr_src[e + 1]);
        float a0 = __ldg(&as_i[s0 * HH + head]);
        float a1 = __ldg(&as_i[s1 * HH + head]);
        float v0[V], v1[V];
        if (V == 2) {
            float2 u0 = ((const float2*)(feat + (size_t)s0 * HH * C))[t];
            float2 u1 = ((const float2*)(feat + (size_t)s1 * HH * C))[t];
            v0[0] = u0.x; v0[1] = u0.y;
            v1[0] = u1.x; v1[1] = u1.y;
        } else {
            v0[0] = feat[(size_t)s0 * HH * C + t];
            v1[0] = feat[(size_t)s1 * HH * C + t];
        }
        float e0 = a0 + adh; e0 = e0 > 0.f ? e0 : NEG_SLOPE * e0;
        float e1 = a1 + adh; e1 = e1 > 0.f ? e1 : NEG_SLOPE * e1;
        float x0 = __expf(e0);
        float x1 = __expf(e1);
        denom += x0 + x1;
#pragma unroll
        for (int j = 0; j < V; j++) acc[j] += x0 * v0[j] + x1 * v1[j];
    }
    if (e < end) {
        int s0 = __ldg(&csr_src[e]);
        float a0 = __ldg(&as_i[s0 * HH + head]);
        float v0[V];
        if (V == 2) {
            float2 u0 = ((const float2*)(feat + (size_t)s0 * HH * C))[t];
            v0[0] = u0.x; v0[1] = u0.y;
        } else {
            v0[0] = feat[(size_t)s0 * HH * C + t];
        }
        float e0 = a0 + adh; e0 = e0 > 0.f ? e0 : NEG_SLOPE * e0;
        float x0 = __expf(e0);
        denom += x0;
#pragma unroll
        for (int j = 0; j < V; j++) acc[j] += x0 * v0[j];
    }

    float inv = 1.f / (denom + EPSV);
#pragma unroll
    for (int j = 0; j < V; j++) sm[t * V + j] = acc[j] * inv;
    __syncthreads();
    if (t < C) {
        float v = 0.25f * (sm[t] + sm[C + t] + sm[2 * C + t] + sm[3 * C + t]) + bias[t];
        if (do_relu) v = fmaxf(v, 0.f);
        out[(size_t)node * C + t] = v;
    }
}

// ---------------- host launcher ----------------
extern "C" void kernel_launch(void* const* d_in, const int* in_sizes, int n_in,
                              void* d_out, int out_size) {
    const float* x   = (const float*)d_in[0];
    const void*  ei  = d_in[1];
    const float* W1  = (const float*)d_in[2];
    const float* as1 = (const float*)d_in[3];
    const float* ad1 = (const float*)d_in[4];
    const float* b1  = (const float*)d_in[5];
    const float* W2  = (const float*)d_in[6];
    const float* as2 = (const float*)d_in[7];
    const float* ad2 = (const float*)d_in[8];
    const float* b2  = (const float*)d_in[9];
    float* out = (float*)d_out;

    float *feat, *hmid, *asb, *adb;
    int *srcp, *dstp, *deg, *rowptr, *cursor, *csr;
    cudaGetSymbolAddress((void**)&feat,   g_feat);
    cudaGetSymbolAddress((void**)&hmid,   g_hmid);
    cudaGetSymbolAddress((void**)&asb,    g_as);
    cudaGetSymbolAddress((void**)&adb,    g_ad);
    cudaGetSymbolAddress((void**)&srcp,   g_src);
    cudaGetSymbolAddress((void**)&dstp,   g_dst);
    cudaGetSymbolAddress((void**)&deg,    g_deg);
    cudaGetSymbolAddress((void**)&rowptr, g_rowptr);
    cudaGetSymbolAddress((void**)&cursor, g_cursor);
    cudaGetSymbolAddress((void**)&csr,    g_csr_src);

    // ---- CSR build (once per call) ----
    zero_deg_kernel<<<256, 256>>>(deg);
    decode_hist_kernel<<<1024, 256>>>(ei, srcp, dstp, deg);
    scan_kernel<<<1, 1024>>>(deg, rowptr, cursor);
    fill_csr_kernel<<<1024, 256>>>(srcp, dstp, cursor, csr);

    // ---- layer 1 ----
    {
        const int M = HH * CC1;  // 256
        dim3 ggrid(M / 64, (NN + 127) / 128);
        gemm_kernel<<<ggrid, 256>>>(x, W1, feat, NN, FIN, M);
        att_dots_kernel<<<(NN * HH * 32 + 255) / 256, 256>>>(feat, as1, ad1, asb, adb, CC1);
        gat_aggregate_kernel<CC1><<<NN, 128>>>(rowptr, csr, asb, adb, feat, b1, hmid, 1);
    }

    // ---- layer 2 ----
    {
        const int M = HH * CC2;  // 128
        dim3 ggrid(M / 64, (NN + 127) / 128);
        gemm_kernel<<<ggrid, 256>>>(hmid, W2, feat, NN, CC1, M);
        att_dots_kernel<<<(NN * HH * 32 + 255) / 256, 256>>>(feat, as2, ad2, asb, adb, CC2);
        gat_aggregate_kernel<CC2><<<NN, 128>>>(rowptr, csr, asb, adb, feat, b2, out, 0);
    }
}

// round 6
// speedup vs baseline: 3.1677x; 1.3308x over previous
#include <cuda_runtime.h>
#include <cstdint>

// ---------------- problem constants ----------------
#define NN   50000
#define EE   800000
#define FIN  128
#define HH   4
#define CC1  64
#define CC2  32
#define NEG_SLOPE 0.2f
#define EPSV 1e-16f

#define SCAN_CHUNK 256
#define NB ((NN + SCAN_CHUNK - 1) / SCAN_CHUNK)   // 196

// ---------------- device scratch (no allocs allowed) ----------------
__device__ float g_feat[NN * HH * CC1];    // layer1: h1 [N,256]; layer2 reuse: h2 [N,128]
__device__ float g_hmid[NN * CC1];         // layer1 output after mean+bias+relu [N,64]
__device__ float g_as[NN * HH];
__device__ float g_ad[NN * HH];
__device__ int   g_src[EE];
__device__ int   g_dst[EE];
__device__ int   g_deg[NN];
__device__ int   g_rowptr[NN + 1];
__device__ int   g_cursor[NN];
__device__ int   g_csr_src[EE];
__device__ int   g_partial[NB];
__device__ int   g_offset[NB];

// ---------------- CSR build kernels ----------------

__global__ void zero_deg_kernel(int* __restrict__ deg) {
    int i = blockIdx.x * blockDim.x + threadIdx.x;
    int stride = gridDim.x * blockDim.x;
    for (; i < NN; i += stride) deg[i] = 0;
}

// Decode edge_index into int src/dst + in-degree histogram.
// Detects int32 vs int64 on device (false-positive prob ~(1/NN)^8 ~= 0).
__global__ void decode_hist_kernel(const void* __restrict__ ei_raw,
                                   int* __restrict__ src, int* __restrict__ dst,
                                   int* __restrict__ deg) {
    const long long* p64 = (const long long*)ei_raw;
    bool is64 = true;
#pragma unroll
    for (int k = 0; k < 8; k++) {
        long long v = p64[k];
        if (v < 0 || v >= NN) { is64 = false; break; }
    }
    int i = blockIdx.x * blockDim.x + threadIdx.x;
    int stride = gridDim.x * blockDim.x;
    if (is64) {
        for (; i < EE; i += stride) {
            int s = (int)p64[i];
            int d = (int)p64[EE + i];
            src[i] = s; dst[i] = d;
            atomicAdd(&deg[d], 1);
        }
    } else {
        const int* p32 = (const int*)ei_raw;
        for (; i < EE; i += stride) {
            int s = p32[i];
            int d = p32[EE + i];
            src[i] = s; dst[i] = d;
            atomicAdd(&deg[d], 1);
        }
    }
}

// Phase A: per-chunk sums.
__global__ void scan_partials_kernel(const int* __restrict__ deg, int* __restrict__ partial) {
    __shared__ int sm[SCAN_CHUNK];
    int b = blockIdx.x, t = threadIdx.x;
    int i = b * SCAN_CHUNK + t;
    sm[t] = (i < NN) ? deg[i] : 0;
    __syncthreads();
#pragma unroll
    for (int off = 128; off; off >>= 1) {
        if (t < off) sm[t] += sm[t + off];
        __syncthreads();
    }
    if (t == 0) partial[b] = sm[0];
}

// Phase B: single-block exclusive scan of NB partials.
__global__ void scan_offsets_kernel(const int* __restrict__ partial,
                                    int* __restrict__ offset, int* __restrict__ rowptr) {
    __shared__ int sm[256];
    int t = threadIdx.x;
    int v = (t < NB) ? partial[t] : 0;
    sm[t] = v;
    __syncthreads();
#pragma unroll
    for (int off = 1; off < 256; off <<= 1) {
        int x = (t >= off) ? sm[t - off] : 0;
        __syncthreads();
        sm[t] += x;
        __syncthreads();
    }
    if (t < NB) offset[t] = sm[t] - v;  // exclusive
    if (t == 0) rowptr[NN] = EE;
}

// Phase C: per-chunk local exclusive scan + block offset -> rowptr/cursor.
__global__ void scan_final_kernel(const int* __restrict__ deg, const int* __restrict__ offset,
                                  int* __restrict__ rowptr, int* __restrict__ cursor) {
    __shared__ int sm[SCAN_CHUNK];
    int b = blockIdx.x, t = threadIdx.x;
    int i = b * SCAN_CHUNK + t;
    int v = (i < NN) ? deg[i] : 0;
    sm[t] = v;
    __syncthreads();
#pragma unroll
    for (int off = 1; off < SCAN_CHUNK; off <<= 1) {
        int x = (t >= off) ? sm[t - off] : 0;
        __syncthreads();
        sm[t] += x;
        __syncthreads();
    }
    if (i < NN) {
        int excl = sm[t] - v + offset[b];
        rowptr[i] = excl;
        cursor[i] = excl;
    }
}

// Scatter edge source ids into CSR slots grouped by dst.
__global__ void fill_csr_kernel(const int* __restrict__ src, const int* __restrict__ dst,
                                int* __restrict__ cursor, int* __restrict__ csr_src) {
    int i = blockIdx.x * blockDim.x + threadIdx.x;
    int stride = gridDim.x * blockDim.x;
    for (; i < EE; i += stride) {
        int d = dst[i];
        int slot = atomicAdd(&cursor[d], 1);
        csr_src[slot] = src[i];
    }
}

// ---------------- fused GEMM + attention-dot epilogue ----------------
// C[n,M] = A[n,K] @ B[K,M]; BM=128, BN=64, BK=16, 256 threads, 8x4 microtile.
// Epilogue: block's 64-col tile aligns to head boundaries (C=64: 1 head; C=32: 2
// heads), so each thread dots acc against att vectors, shfl-reduces across the
// col-group lanes, and writes a_s/a_d directly. Removes the att_dots pass.
template <int C>
__global__ void __launch_bounds__(256) gemm_fused_kernel(
        const float* __restrict__ A, const float* __restrict__ B,
        float* __restrict__ Cout, int n, int K,
        const float* __restrict__ att_s, const float* __restrict__ att_d,
        float* __restrict__ as_o, float* __restrict__ ad_o) {
    const int M = HH * C;
    __shared__ float As[16][128];
    __shared__ float Bs[16][64];
    int tid = threadIdx.x;
    int tx = tid & 15;        // col group (4 cols)
    int ty = tid >> 4;        // row group (8 rows)
    int rowBase = blockIdx.y * 128;
    int colBase = blockIdx.x * 64;

    // attention vector slice for this thread's 4 columns
    int head, cloc;
    if (C == 64) { head = blockIdx.x;               cloc = tx * 4; }
    else         { head = blockIdx.x * 2 + (tx >> 3); cloc = (tx & 7) * 4; }
    float satt[4], datt[4];
#pragma unroll
    for (int j = 0; j < 4; j++) {
        satt[j] = __ldg(&att_s[head * C + cloc + j]);
        datt[j] = __ldg(&att_d[head * C + cloc + j]);
    }

    float acc[8][4];
#pragma unroll
    for (int i = 0; i < 8; i++)
#pragma unroll
        for (int j = 0; j < 4; j++) acc[i][j] = 0.f;

    for (int k0 = 0; k0 < K; k0 += 16) {
        // A tile: 128x16 floats = 512 float4, 2 per thread, transposed into As
#pragma unroll
        for (int q = 0; q < 2; q++) {
            int idx = tid + q * 256;
            int r = idx >> 2;
            int kq = idx & 3;
            int row = rowBase + r;
            float4 v = (row < n) ? ((const float4*)(A + (size_t)row * K + k0))[kq]
                                 : make_float4(0.f, 0.f, 0.f, 0.f);
            As[kq * 4 + 0][r] = v.x;
            As[kq * 4 + 1][r] = v.y;
            As[kq * 4 + 2][r] = v.z;
            As[kq * 4 + 3][r] = v.w;
        }
        // B tile: 16x64 floats = 256 float4, 1 per thread
        {
            int r = tid >> 4;
            int cq = tid & 15;
            float4 v = ((const float4*)(B + (size_t)(k0 + r) * M + colBase))[cq];
            ((float4*)&Bs[r][0])[cq] = v;
        }
        __syncthreads();
#pragma unroll
        for (int kk = 0; kk < 16; kk++) {
            float a[8], b[4];
            float4 a0 = ((const float4*)&As[kk][0])[ty * 2];
            float4 a1 = ((const float4*)&As[kk][0])[ty * 2 + 1];
            a[0] = a0.x; a[1] = a0.y; a[2] = a0.z; a[3] = a0.w;
            a[4] = a1.x; a[5] = a1.y; a[6] = a1.z; a[7] = a1.w;
            float4 bv = ((const float4*)&Bs[kk][0])[tx];
            b[0] = bv.x; b[1] = bv.y; b[2] = bv.z; b[3] = bv.w;
#pragma unroll
            for (int i = 0; i < 8; i++)
#pragma unroll
                for (int j = 0; j < 4; j++) acc[i][j] += a[i] * b[j];
        }
        __syncthreads();
    }

    const int W = (C == 64) ? 16 : 8;   // shfl reduction width (lanes per head seg)
#pragma unroll
    for (int i = 0; i < 8; i++) {
        int r = rowBase + ty * 8 + i;
        if (r < n) {
            float4 v = make_float4(acc[i][0], acc[i][1], acc[i][2], acc[i][3]);
            ((float4*)(Cout + (size_t)r * M + colBase))[tx] = v;
        }
        float ps = acc[i][0] * satt[0] + acc[i][1] * satt[1] +
                   acc[i][2] * satt[2] + acc[i][3] * satt[3];
        float pd = acc[i][0] * datt[0] + acc[i][1] * datt[1] +
                   acc[i][2] * datt[2] + acc[i][3] * datt[3];
#pragma unroll
        for (int o = W / 2; o; o >>= 1) {
            ps += __shfl_down_sync(0xffffffffu, ps, o, W);
            pd += __shfl_down_sync(0xffffffffu, pd, o, W);
        }
        if ((tx & (W - 1)) == 0 && r < n) {
            as_o[r * HH + head] = ps;
            ad_o[r * HH + head] = pd;
        }
    }
}

// ---------------- fused pull-mode GAT aggregation ----------------
// One block (128 thr) per destination node; warp w handles head w.
template <int C>
__global__ void __launch_bounds__(128) gat_aggregate_kernel(
        const int* __restrict__ rowptr,
        const int* __restrict__ csr_src,
        const float* __restrict__ as_i,
        const float* __restrict__ ad_i,
        const float* __restrict__ feat,
        const float* __restrict__ bias,
        float* __restrict__ out, int do_relu) {
    constexpr int V = C / 32;            // floats per thread (2 for C=64, 1 for C=32)
    __shared__ float sm[HH * C];
    const int node = blockIdx.x;
    const int t = threadIdx.x;
    const int head = t >> 5;
    const float adh = ad_i[node * HH + head];
    int beg = rowptr[node], end = rowptr[node + 1];
    float acc[V];
#pragma unroll
    for (int j = 0; j < V; j++) acc[j] = 0.f;
    float denom = 0.f;

    int e = beg;
    for (; e + 4 <= end; e += 4) {
        int s0 = __ldg(&csr_src[e]);
        int s1 = __ldg(&csr_src[e + 1]);
        int s2 = __ldg(&csr_src[e + 2]);
        int s3 = __ldg(&csr_src[e + 3]);
        float a0 = __ldg(&as_i[s0 * HH + head]);
        float a1 = __ldg(&as_i[s1 * HH + head]);
        float a2 = __ldg(&as_i[s2 * HH + head]);
        float a3 = __ldg(&as_i[s3 * HH + head]);
        float v0[V], v1[V], v2[V], v3[V];
        if (V == 2) {
            float2 u0 = ((const float2*)(feat + (size_t)s0 * HH * C))[t];
            float2 u1 = ((const float2*)(feat + (size_t)s1 * HH * C))[t];
            float2 u2 = ((const float2*)(feat + (size_t)s2 * HH * C))[t];
            float2 u3 = ((const float2*)(feat + (size_t)s3 * HH * C))[t];
            v0[0] = u0.x; v0[1] = u0.y; v1[0] = u1.x; v1[1] = u1.y;
            v2[0] = u2.x; v2[1] = u2.y; v3[0] = u3.x; v3[1] = u3.y;
        } else {
            v0[0] = feat[(size_t)s0 * HH * C + t];
            v1[0] = feat[(size_t)s1 * HH * C + t];
            v2[0] = feat[(size_t)s2 * HH * C + t];
            v3[0] = feat[(size_t)s3 * HH * C + t];
        }
        float e0 = a0 + adh; e0 = e0 > 0.f ? e0 : NEG_SLOPE * e0;
        float e1 = a1 + adh; e1 = e1 > 0.f ? e1 : NEG_SLOPE * e1;
        float e2 = a2 + adh; e2 = e2 > 0.f ? e2 : NEG_SLOPE * e2;
        float e3 = a3 + adh; e3 = e3 > 0.f ? e3 : NEG_SLOPE * e3;
        float x0 = __expf(e0), x1 = __expf(e1), x2 = __expf(e2), x3 = __expf(e3);
        denom += (x0 + x1) + (x2 + x3);
#pragma unroll
        for (int j = 0; j < V; j++)
            acc[j] += (x0 * v0[j] + x1 * v1[j]) + (x2 * v2[j] + x3 * v3[j]);
    }
    for (; e < end; e++) {
        int s0 = __ldg(&csr_src[e]);
        float a0 = __ldg(&as_i[s0 * HH + head]);
        float v0[V];
        if (V == 2) {
            float2 u0 = ((const float2*)(feat + (size_t)s0 * HH * C))[t];
            v0[0] = u0.x; v0[1] = u0.y;
        } else {
            v0[0] = feat[(size_t)s0 * HH * C + t];
        }
        float e0 = a0 + adh; e0 = e0 > 0.f ? e0 : NEG_SLOPE * e0;
        float x0 = __expf(e0);
        denom += x0;
#pragma unroll
        for (int j = 0; j < V; j++) acc[j] += x0 * v0[j];
    }

    float inv = 1.f / (denom + EPSV);
#pragma unroll
    for (int j = 0; j < V; j++) sm[t * V + j] = acc[j] * inv;
    __syncthreads();
    if (t < C) {
        float v = 0.25f * (sm[t] + sm[C + t] + sm[2 * C + t] + sm[3 * C + t]) + bias[t];
        if (do_relu) v = fmaxf(v, 0.f);
        out[(size_t)node * C + t] = v;
    }
}

// ---------------- host launcher ----------------
extern "C" void kernel_launch(void* const* d_in, const int* in_sizes, int n_in,
                              void* d_out, int out_size) {
    const float* x   = (const float*)d_in[0];
    const void*  ei  = d_in[1];
    const float* W1  = (const float*)d_in[2];
    const float* as1 = (const float*)d_in[3];
    const float* ad1 = (const float*)d_in[4];
    const float* b1  = (const float*)d_in[5];
    const float* W2  = (const float*)d_in[6];
    const float* as2 = (const float*)d_in[7];
    const float* ad2 = (const float*)d_in[8];
    const float* b2  = (const float*)d_in[9];
    float* out = (float*)d_out;

    float *feat, *hmid, *asb, *adb;
    int *srcp, *dstp, *deg, *rowptr, *cursor, *csr, *partial, *offset;
    cudaGetSymbolAddress((void**)&feat,    g_feat);
    cudaGetSymbolAddress((void**)&hmid,    g_hmid);
    cudaGetSymbolAddress((void**)&asb,     g_as);
    cudaGetSymbolAddress((void**)&adb,     g_ad);
    cudaGetSymbolAddress((void**)&srcp,    g_src);
    cudaGetSymbolAddress((void**)&dstp,    g_dst);
    cudaGetSymbolAddress((void**)&deg,     g_deg);
    cudaGetSymbolAddress((void**)&rowptr,  g_rowptr);
    cudaGetSymbolAddress((void**)&cursor,  g_cursor);
    cudaGetSymbolAddress((void**)&csr,     g_csr_src);
    cudaGetSymbolAddress((void**)&partial, g_partial);
    cudaGetSymbolAddress((void**)&offset,  g_offset);

    // ---- CSR build ----
    zero_deg_kernel<<<256, 256>>>(deg);
    decode_hist_kernel<<<1024, 256>>>(ei, srcp, dstp, deg);
    scan_partials_kernel<<<NB, SCAN_CHUNK>>>(deg, partial);
    scan_offsets_kernel<<<1, 256>>>(partial, offset, rowptr);
    scan_final_kernel<<<NB, SCAN_CHUNK>>>(deg, offset, rowptr, cursor);
    fill_csr_kernel<<<1024, 256>>>(srcp, dstp, cursor, csr);

    // ---- layer 1 ----
    {
        dim3 ggrid(HH * CC1 / 64, (NN + 127) / 128);
        gemm_fused_kernel<CC1><<<ggrid, 256>>>(x, W1, feat, NN, FIN, as1, ad1, asb, adb);
        gat_aggregate_kernel<CC1><<<NN, 128>>>(rowptr, csr, asb, adb, feat, b1, hmid, 1);
    }

    // ---- layer 2 ----
    {
        dim3 ggrid(HH * CC2 / 64, (NN + 127) / 128);
        gemm_fused_kernel<CC2><<<ggrid, 256>>>(hmid, W2, feat, NN, CC1, as2, ad2, asb, adb);
        gat_aggregate_kernel<CC2><<<NN, 128>>>(rowptr, csr, asb, adb, feat, b2, out, 0);
    }
}